// round 2
// baseline (speedup 1.0000x reference)
#include <cuda_runtime.h>

#define AA 16      // agents
#define EE 128     // embed dim
#define EP 132     // padded row (bank-conflict-free strided row access)
#define NH 8       // heads
#define DH 16      // head dim
#define NEGV (-1e9f)

// Y[r][j] = sum_k X[r][k] * W[k][j], j = this thread's column.
__device__ __forceinline__ void mm(const float (*X)[EP], const float* __restrict__ W,
                                   int j, float acc[AA]) {
#pragma unroll
    for (int r = 0; r < AA; r++) acc[r] = 0.f;
#pragma unroll 4
    for (int k = 0; k < EE; k += 4) {
        float w0 = __ldg(&W[(k + 0) * EE + j]);
        float w1 = __ldg(&W[(k + 1) * EE + j]);
        float w2 = __ldg(&W[(k + 2) * EE + j]);
        float w3 = __ldg(&W[(k + 3) * EE + j]);
#pragma unroll
        for (int r = 0; r < AA; r++) {
            const float4 xv = *reinterpret_cast<const float4*>(&X[r][k]);
            float a = acc[r];
            a = fmaf(xv.x, w0, a);
            a = fmaf(xv.y, w1, a);
            a = fmaf(xv.z, w2, a);
            a = fmaf(xv.w, w3, a);
            acc[r] = a;
        }
    }
}

// In-place layernorm over the 128-wide rows of X. 4 warps, each handles 4 rows.
__device__ __forceinline__ void lnorm(float (*X)[EP], const float* __restrict__ g,
                                      const float* __restrict__ b, int t) {
    const int warp = t >> 5, lane = t & 31;
    const float4 g4 = *reinterpret_cast<const float4*>(&g[lane * 4]);
    const float4 b4 = *reinterpret_cast<const float4*>(&b[lane * 4]);
#pragma unroll
    for (int rr = 0; rr < 4; rr++) {
        const int r = warp + rr * 4;
        float4 x = *reinterpret_cast<float4*>(&X[r][lane * 4]);
        float s  = x.x + x.y + x.z + x.w;
        float ss = fmaf(x.x, x.x, fmaf(x.y, x.y, fmaf(x.z, x.z, x.w * x.w)));
#pragma unroll
        for (int o = 16; o > 0; o >>= 1) {
            s  += __shfl_xor_sync(0xffffffffu, s, o);
            ss += __shfl_xor_sync(0xffffffffu, ss, o);
        }
        const float mu  = s * (1.f / 128.f);
        const float var = ss * (1.f / 128.f) - mu * mu;
        const float inv = rsqrtf(var + 1e-5f);
        x.x = (x.x - mu) * inv * g4.x + b4.x;
        x.y = (x.y - mu) * inv * g4.y + b4.y;
        x.z = (x.z - mu) * inv * g4.z + b4.z;
        x.w = (x.w - mu) * inv * g4.w + b4.w;
        *reinterpret_cast<float4*>(&X[r][lane * 4]) = x;
    }
}

__global__ void __launch_bounds__(128)
conflict_model_kernel(
    const float* __restrict__ agent_embed,  // [B,16,128]
    const float* __restrict__ city_embed,   // [B,128,128]
    const int*   __restrict__ acts,         // [B,16]
    const float* __restrict__ Wq,  const float* __restrict__ Wk,
    const float* __restrict__ Wv,  const float* __restrict__ Wo,
    const float* __restrict__ ln1_g, const float* __restrict__ ln1_b,
    const float* __restrict__ W1,  const float* __restrict__ b1v,
    const float* __restrict__ W2,  const float* __restrict__ b2v,
    const float* __restrict__ ln2_g, const float* __restrict__ ln2_b,
    const float* __restrict__ Wqs, const float* __restrict__ Wks,
    float* __restrict__ out)                // [B,16,16]
{
    const int b = blockIdx.x;
    const int t = threadIdx.x;  // 0..127

    __shared__ float s_agent[AA][EP];
    __shared__ float s_x[AA][EP];    // selected -> cac2
    __shared__ float s_b1[AA][EP];   // q -> attn_out -> qs
    __shared__ float s_b2[AA][EP];   // k -> h(postLN1) -> ks
    __shared__ float s_b3[AA][EP];   // v -> ffn hidden
    __shared__ int      s_acts[AA];
    __shared__ unsigned s_mask[AA];  // bit j set = blocked (mask True)

    // ---- load agent rows + acts ----
    const float* ag = agent_embed + (size_t)b * AA * EE;
    if (t < AA) s_acts[t] = acts[b * AA + t];
#pragma unroll
    for (int r = 0; r < AA; r++) s_agent[r][t] = ag[r * EE + t];
    __syncthreads();

    // ---- conflict mask + gather selected city embeddings ----
    if (t < AA) {
        const int ai = s_acts[t];
        unsigned m = 0;
#pragma unroll
        for (int j = 0; j < AA; j++) {
            const bool conflict = (ai == 0) ? (j == t) : (s_acts[j] == ai);
            if (!conflict) m |= (1u << j);
        }
        s_mask[t] = m;
    }
    const float* ce = city_embed + (size_t)b * 128 * EE;
#pragma unroll
    for (int r = 0; r < AA; r++) s_x[r][t] = ce[s_acts[r] * EE + t];
    __syncthreads();

    float acc[AA];

    // ---- q,k,v projections (q pre-scaled by 1/sqrt(dh)=0.25) ----
    mm(s_x, Wq, t, acc);
#pragma unroll
    for (int r = 0; r < AA; r++) s_b1[r][t] = acc[r] * 0.25f;
    mm(s_agent, Wk, t, acc);
#pragma unroll
    for (int r = 0; r < AA; r++) s_b2[r][t] = acc[r];
    mm(s_agent, Wv, t, acc);
#pragma unroll
    for (int r = 0; r < AA; r++) s_b3[r][t] = acc[r];
    __syncthreads();

    // ---- 8-head masked attention: thread = (head h, query qi) ----
    {
        const int h = t >> 4, qi = t & 15;
        float qreg[DH];
#pragma unroll
        for (int d = 0; d < DH; d += 4) {
            const float4 q4 = *reinterpret_cast<const float4*>(&s_b1[qi][h * DH + d]);
            qreg[d] = q4.x; qreg[d + 1] = q4.y; qreg[d + 2] = q4.z; qreg[d + 3] = q4.w;
        }
        float sc[AA];
#pragma unroll
        for (int ki = 0; ki < AA; ki++) {
            float s = 0.f;
#pragma unroll
            for (int d = 0; d < DH; d += 4) {
                const float4 k4 = *reinterpret_cast<const float4*>(&s_b2[ki][h * DH + d]);
                s = fmaf(qreg[d], k4.x, s);
                s = fmaf(qreg[d + 1], k4.y, s);
                s = fmaf(qreg[d + 2], k4.z, s);
                s = fmaf(qreg[d + 3], k4.w, s);
            }
            sc[ki] = s;
        }
        const unsigned m = s_mask[qi];
        float mx = -3.4e38f;
#pragma unroll
        for (int ki = 0; ki < AA; ki++) {
            if (m & (1u << ki)) sc[ki] = NEGV;
            mx = fmaxf(mx, sc[ki]);
        }
        float sum = 0.f;
#pragma unroll
        for (int ki = 0; ki < AA; ki++) { sc[ki] = __expf(sc[ki] - mx); sum += sc[ki]; }
        const float inv = 1.f / sum;
        float o[DH];
#pragma unroll
        for (int d = 0; d < DH; d++) o[d] = 0.f;
#pragma unroll
        for (int ki = 0; ki < AA; ki++) {
            const float p = sc[ki];
#pragma unroll
            for (int d = 0; d < DH; d += 4) {
                const float4 v4 = *reinterpret_cast<const float4*>(&s_b3[ki][h * DH + d]);
                o[d]     = fmaf(p, v4.x, o[d]);
                o[d + 1] = fmaf(p, v4.y, o[d + 1]);
                o[d + 2] = fmaf(p, v4.z, o[d + 2]);
                o[d + 3] = fmaf(p, v4.w, o[d + 3]);
            }
        }
        __syncthreads();  // all reads of q (s_b1) complete before overwrite
#pragma unroll
        for (int d = 0; d < DH; d++) s_b1[qi][h * DH + d] = o[d] * inv;
    }
    __syncthreads();

    // ---- attn_out @ Wo + residual(selected) -> s_b2; LN1 ----
    mm(s_b1, Wo, t, acc);
#pragma unroll
    for (int r = 0; r < AA; r++) s_b2[r][t] = acc[r] + s_x[r][t];
    __syncthreads();
    lnorm(s_b2, ln1_g, ln1_b, t);
    __syncthreads();

    // ---- FFN hidden = relu(h @ W1 + b1) -> s_b3 ----
    mm(s_b2, W1, t, acc);
    {
        const float bias1 = __ldg(&b1v[t]);
#pragma unroll
        for (int r = 0; r < AA; r++) s_b3[r][t] = fmaxf(acc[r] + bias1, 0.f);
    }
    __syncthreads();

    // ---- FFN out + residual(h) -> s_x; LN2 ----
    mm(s_b3, W2, t, acc);
    {
        const float bias2 = __ldg(&b2v[t]);
#pragma unroll
        for (int r = 0; r < AA; r++) s_x[r][t] = acc[r] + bias2 + s_b2[r][t];
    }
    __syncthreads();
    lnorm(s_x, ln2_g, ln2_b, t);
    __syncthreads();

    // ---- qs = cac @ Wq_s -> s_b1; ks = agent @ Wk_s -> s_b2 ----
    mm(s_x, Wqs, t, acc);
#pragma unroll
    for (int r = 0; r < AA; r++) s_b1[r][t] = acc[r];
    mm(s_agent, Wks, t, acc);
#pragma unroll
    for (int r = 0; r < AA; r++) s_b2[r][t] = acc[r];
    __syncthreads();

    // ---- single-head logits: thread t -> qi = t>>3, ki in {t&7, (t&7)+8} ----
    {
        const int qi = t >> 3;
        const int k0 = t & 7;
#pragma unroll
        for (int kk = 0; kk < 2; kk++) {
            const int ki = k0 + kk * 8;
            float s = 0.f;
#pragma unroll 8
            for (int e = 0; e < EE; e += 4) {
                const float4 a4 = *reinterpret_cast<const float4*>(&s_b1[qi][e]);
                const float4 c4 = *reinterpret_cast<const float4*>(&s_b2[ki][e]);
                s = fmaf(a4.x, c4.x, s);
                s = fmaf(a4.y, c4.y, s);
                s = fmaf(a4.z, c4.z, s);
                s = fmaf(a4.w, c4.w, s);
            }
            float lg = 10.f * tanhf(s * 0.08838834764831845f);
            if (s_mask[qi] & (1u << ki)) lg = NEGV;
            out[(size_t)b * (AA * AA) + qi * AA + ki] = lg;
        }
    }
}

extern "C" void kernel_launch(void* const* d_in, const int* in_sizes, int n_in,
                              void* d_out, int out_size) {
    const float* agent_embed = (const float*)d_in[0];
    const float* city_embed  = (const float*)d_in[1];
    const int*   acts        = (const int*)d_in[2];
    const float* Wq    = (const float*)d_in[3];
    const float* Wk    = (const float*)d_in[4];
    const float* Wv    = (const float*)d_in[5];
    const float* Wo    = (const float*)d_in[6];
    const float* ln1_g = (const float*)d_in[7];
    const float* ln1_b = (const float*)d_in[8];
    const float* W1    = (const float*)d_in[9];
    const float* b1v   = (const float*)d_in[10];
    const float* W2    = (const float*)d_in[11];
    const float* b2v   = (const float*)d_in[12];
    const float* ln2_g = (const float*)d_in[13];
    const float* ln2_b = (const float*)d_in[14];
    const float* Wqs   = (const float*)d_in[15];
    const float* Wks   = (const float*)d_in[16];

    const int B = in_sizes[0] / (AA * EE);  // agent_embed elements / (16*128)

    conflict_model_kernel<<<B, 128>>>(
        agent_embed, city_embed, acts,
        Wq, Wk, Wv, Wo, ln1_g, ln1_b,
        W1, b1v, W2, b2v, ln2_g, ln2_b,
        Wqs, Wks, (float*)d_out);
}

// round 3
// speedup vs baseline: 4.2130x; 4.2130x over previous
#include <cuda_runtime.h>
#include <cuda_bf16.h>

#define AA 16      // agents
#define EE 128     // embed dim
#define EP 132     // padded fp32 row (conflict-free strided access)
#define NEGV (-1e9f)

// Packed bf16 weight fragments: [matrix 8][ntile 16][kstep 8][lane 32] of uint2{b0,b1}.
// b0 = {W[k][n], W[k+1][n]}, b1 = {W[k+8][n], W[k+9][n]} for this lane's (n,k).
__device__ uint2 g_wpack[8 * 16 * 8 * 32];

__device__ __forceinline__ unsigned pk2(float lo, float hi) {
    unsigned r;
    asm("cvt.rn.bf16x2.f32 %0, %1, %2;" : "=r"(r) : "f"(hi), "f"(lo));
    return r;
}

// Load 2 consecutive fp32 from shared, pack to bf16x2 (lo = p[0], hi = p[1]).
__device__ __forceinline__ unsigned pkx(const float* p) {
    const float2 v = *reinterpret_cast<const float2*>(p);
    return pk2(v.x, v.y);
}

__device__ __forceinline__ void mma16816(float& d0, float& d1, float& d2, float& d3,
                                         unsigned a0, unsigned a1, unsigned a2, unsigned a3,
                                         unsigned b0, unsigned b1) {
    asm("mma.sync.aligned.m16n8k16.row.col.f32.bf16.bf16.f32 "
        "{%0,%1,%2,%3}, {%4,%5,%6,%7}, {%8,%9}, {%0,%1,%2,%3};"
        : "+f"(d0), "+f"(d1), "+f"(d2), "+f"(d3)
        : "r"(a0), "r"(a1), "r"(a2), "r"(a3), "r"(b0), "r"(b1));
}

// ---- prepass: repack 8 fp32 [128][128] weights into per-lane fragment order ----
__global__ void __launch_bounds__(128) pack_weights_kernel(
    const float* __restrict__ Wq, const float* __restrict__ Wk,
    const float* __restrict__ Wv, const float* __restrict__ Wo,
    const float* __restrict__ W1, const float* __restrict__ W2,
    const float* __restrict__ Wqs, const float* __restrict__ Wks)
{
    const int idx = blockIdx.x * blockDim.x + threadIdx.x;   // 0..32767
    const int l  = idx & 31;
    const int kk = (idx >> 5) & 7;
    const int nt = (idx >> 8) & 15;
    const int m  = idx >> 12;
    const float* W;
    float sc = 1.f;
    switch (m) {
        case 0: W = Wq; sc = 0.25f; break;   // fold 1/sqrt(dh)=0.25 into Wq
        case 1: W = Wk; break;
        case 2: W = Wv; break;
        case 3: W = Wo; break;
        case 4: W = W1; break;
        case 5: W = W2; break;
        case 6: W = Wqs; break;
        default: W = Wks; break;
    }
    const int n = nt * 8 + (l >> 2);
    const int k = kk * 16 + 2 * (l & 3);
    const float v00 = W[(k + 0) * EE + n] * sc;
    const float v01 = W[(k + 1) * EE + n] * sc;
    const float v10 = W[(k + 8) * EE + n] * sc;
    const float v11 = W[(k + 9) * EE + n] * sc;
    g_wpack[idx] = make_uint2(pk2(v00, v01), pk2(v10, v11));
}

// ---- warp-cooperative 16x128x128 GEMM: Y = X @ W (+epilogue). Warp w owns cols [32w,32w+32). ----
enum { MRAW = 0, MRES = 1, MBRELU = 2, MBRES = 3 };

template<int MODE>
__device__ __forceinline__ void mm_mma(const float (*X)[EP], const uint2* __restrict__ Wp,
                                       float (*Y)[EP], const float (*R)[EP],
                                       const float* __restrict__ bias, int t)
{
    const int w = t >> 5, l = t & 31;
    const int r0 = l >> 2;           // 0..7
    const int cq = 2 * (l & 3);      // 0,2,4,6
    float acc[4][4];
#pragma unroll
    for (int i = 0; i < 4; i++) { acc[i][0] = acc[i][1] = acc[i][2] = acc[i][3] = 0.f; }
#pragma unroll
    for (int kk = 0; kk < 8; kk++) {
        const int k = kk * 16;
        const unsigned a0 = pkx(&X[r0][k + cq]);
        const unsigned a1 = pkx(&X[r0 + 8][k + cq]);
        const unsigned a2 = pkx(&X[r0][k + cq + 8]);
        const unsigned a3 = pkx(&X[r0 + 8][k + cq + 8]);
#pragma unroll
        for (int nt = 0; nt < 4; nt++) {
            const uint2 bfr = __ldg(&Wp[((w * 4 + nt) * 8 + kk) * 32 + l]);
            mma16816(acc[nt][0], acc[nt][1], acc[nt][2], acc[nt][3],
                     a0, a1, a2, a3, bfr.x, bfr.y);
        }
    }
#pragma unroll
    for (int nt = 0; nt < 4; nt++) {
        const int nb = (w * 4 + nt) * 8 + cq;
        float x0 = acc[nt][0], x1 = acc[nt][1], x2 = acc[nt][2], x3 = acc[nt][3];
        if (MODE == MRES) {
            const float2 ra = *reinterpret_cast<const float2*>(&R[r0][nb]);
            const float2 rb = *reinterpret_cast<const float2*>(&R[r0 + 8][nb]);
            x0 += ra.x; x1 += ra.y; x2 += rb.x; x3 += rb.y;
        } else if (MODE == MBRELU) {
            const float2 bv = *reinterpret_cast<const float2*>(&bias[nb]);
            x0 = fmaxf(x0 + bv.x, 0.f); x1 = fmaxf(x1 + bv.y, 0.f);
            x2 = fmaxf(x2 + bv.x, 0.f); x3 = fmaxf(x3 + bv.y, 0.f);
        } else if (MODE == MBRES) {
            const float2 bv = *reinterpret_cast<const float2*>(&bias[nb]);
            const float2 ra = *reinterpret_cast<const float2*>(&R[r0][nb]);
            const float2 rb = *reinterpret_cast<const float2*>(&R[r0 + 8][nb]);
            x0 += bv.x + ra.x; x1 += bv.y + ra.y;
            x2 += bv.x + rb.x; x3 += bv.y + rb.y;
        }
        *reinterpret_cast<float2*>(&Y[r0][nb])     = make_float2(x0, x1);
        *reinterpret_cast<float2*>(&Y[r0 + 8][nb]) = make_float2(x2, x3);
    }
}

// In-place layernorm over 128-wide rows. 4 warps, each 4 rows.
__device__ __forceinline__ void lnorm(float (*X)[EP], const float* __restrict__ g,
                                      const float* __restrict__ b, int t) {
    const int warp = t >> 5, lane = t & 31;
    const float4 g4 = *reinterpret_cast<const float4*>(&g[lane * 4]);
    const float4 b4 = *reinterpret_cast<const float4*>(&b[lane * 4]);
#pragma unroll
    for (int rr = 0; rr < 4; rr++) {
        const int r = warp + rr * 4;
        float4 x = *reinterpret_cast<float4*>(&X[r][lane * 4]);
        float s  = x.x + x.y + x.z + x.w;
        float ss = fmaf(x.x, x.x, fmaf(x.y, x.y, fmaf(x.z, x.z, x.w * x.w)));
#pragma unroll
        for (int o = 16; o > 0; o >>= 1) {
            s  += __shfl_xor_sync(0xffffffffu, s, o);
            ss += __shfl_xor_sync(0xffffffffu, ss, o);
        }
        const float mu  = s * (1.f / 128.f);
        const float var = ss * (1.f / 128.f) - mu * mu;
        const float inv = rsqrtf(var + 1e-5f);
        x.x = (x.x - mu) * inv * g4.x + b4.x;
        x.y = (x.y - mu) * inv * g4.y + b4.y;
        x.z = (x.z - mu) * inv * g4.z + b4.z;
        x.w = (x.w - mu) * inv * g4.w + b4.w;
        *reinterpret_cast<float4*>(&X[r][lane * 4]) = x;
    }
}

__global__ void __launch_bounds__(128)
conflict_model_kernel(
    const float* __restrict__ agent_embed,  // [B,16,128]
    const float* __restrict__ city_embed,   // [B,128,128]
    const int*   __restrict__ acts,         // [B,16]
    const float* __restrict__ ln1_g, const float* __restrict__ ln1_b,
    const float* __restrict__ b1v,  const float* __restrict__ b2v,
    const float* __restrict__ ln2_g, const float* __restrict__ ln2_b,
    float* __restrict__ out)                // [B,16,16]
{
    const int b = blockIdx.x;
    const int t = threadIdx.x;  // 0..127

    __shared__ float s_agent[AA][EP];
    __shared__ float s_x[AA][EP];    // selected -> cac2
    __shared__ float s_b1[AA][EP];   // q -> attn_out -> qs
    __shared__ float s_b2[AA][EP];   // k -> h(postLN1) -> ks
    __shared__ float s_b3[AA][EP];   // v -> ffn hidden
    __shared__ int      s_acts[AA];
    __shared__ unsigned s_mask[AA];  // bit j set = blocked

    // ---- load agent rows + acts ----
    const float* ag = agent_embed + (size_t)b * AA * EE;
    if (t < AA) s_acts[t] = acts[b * AA + t];
#pragma unroll
    for (int r = 0; r < AA; r++) s_agent[r][t] = ag[r * EE + t];
    __syncthreads();

    // ---- conflict mask + gather selected city embeddings ----
    if (t < AA) {
        const int ai = s_acts[t];
        unsigned m = 0;
#pragma unroll
        for (int j = 0; j < AA; j++) {
            const bool conflict = (ai == 0) ? (j == t) : (s_acts[j] == ai);
            if (!conflict) m |= (1u << j);
        }
        s_mask[t] = m;
    }
    const float* ce = city_embed + (size_t)b * 128 * EE;
#pragma unroll
    for (int r = 0; r < AA; r++) s_x[r][t] = ce[s_acts[r] * EE + t];
    __syncthreads();

    // ---- q (pre-scaled via packed Wq), k, v projections ----
    mm_mma<MRAW>(s_x,     g_wpack + 0 * 4096, s_b1, nullptr, nullptr, t);
    mm_mma<MRAW>(s_agent, g_wpack + 1 * 4096, s_b2, nullptr, nullptr, t);
    mm_mma<MRAW>(s_agent, g_wpack + 2 * 4096, s_b3, nullptr, nullptr, t);
    __syncthreads();

    // ---- 8-head masked attention: thread = (head h, query qi) ----
    {
        const int h = t >> 4, qi = t & 15;
        float qreg[16];
#pragma unroll
        for (int d = 0; d < 16; d += 4) {
            const float4 q4 = *reinterpret_cast<const float4*>(&s_b1[qi][h * 16 + d]);
            qreg[d] = q4.x; qreg[d + 1] = q4.y; qreg[d + 2] = q4.z; qreg[d + 3] = q4.w;
        }
        float sc[AA];
#pragma unroll
        for (int ki = 0; ki < AA; ki++) {
            float s = 0.f;
#pragma unroll
            for (int d = 0; d < 16; d += 4) {
                const float4 k4 = *reinterpret_cast<const float4*>(&s_b2[ki][h * 16 + d]);
                s = fmaf(qreg[d], k4.x, s);
                s = fmaf(qreg[d + 1], k4.y, s);
                s = fmaf(qreg[d + 2], k4.z, s);
                s = fmaf(qreg[d + 3], k4.w, s);
            }
            sc[ki] = s;
        }
        const unsigned m = s_mask[qi];
        float mx = -3.4e38f;
#pragma unroll
        for (int ki = 0; ki < AA; ki++) {
            if (m & (1u << ki)) sc[ki] = NEGV;
            mx = fmaxf(mx, sc[ki]);
        }
        float sum = 0.f;
#pragma unroll
        for (int ki = 0; ki < AA; ki++) { sc[ki] = __expf(sc[ki] - mx); sum += sc[ki]; }
        const float inv = 1.f / sum;
        float o[16];
#pragma unroll
        for (int d = 0; d < 16; d++) o[d] = 0.f;
#pragma unroll
        for (int ki = 0; ki < AA; ki++) {
            const float p = sc[ki];
#pragma unroll
            for (int d = 0; d < 16; d += 4) {
                const float4 v4 = *reinterpret_cast<const float4*>(&s_b3[ki][h * 16 + d]);
                o[d]     = fmaf(p, v4.x, o[d]);
                o[d + 1] = fmaf(p, v4.y, o[d + 1]);
                o[d + 2] = fmaf(p, v4.z, o[d + 2]);
                o[d + 3] = fmaf(p, v4.w, o[d + 3]);
            }
        }
        __syncthreads();  // all reads of q (s_b1) done before overwrite
#pragma unroll
        for (int d = 0; d < 16; d++) s_b1[qi][h * 16 + d] = o[d] * inv;
    }
    __syncthreads();

    // ---- attn_out @ Wo + selected -> s_b2; LN1 ----
    mm_mma<MRES>(s_b1, g_wpack + 3 * 4096, s_b2, s_x, nullptr, t);
    __syncthreads();
    lnorm(s_b2, ln1_g, ln1_b, t);
    __syncthreads();

    // ---- FFN hidden = relu(h @ W1 + b1) -> s_b3 ----
    mm_mma<MBRELU>(s_b2, g_wpack + 4 * 4096, s_b3, nullptr, b1v, t);
    __syncthreads();

    // ---- FFN out + b2 + residual(h) -> s_x; LN2 ----
    mm_mma<MBRES>(s_b3, g_wpack + 5 * 4096, s_x, s_b2, b2v, t);
    __syncthreads();
    lnorm(s_x, ln2_g, ln2_b, t);
    __syncthreads();

    // ---- qs = cac @ Wq_s -> s_b1; ks = agent @ Wk_s -> s_b2 ----
    mm_mma<MRAW>(s_x,     g_wpack + 6 * 4096, s_b1, nullptr, nullptr, t);
    mm_mma<MRAW>(s_agent, g_wpack + 7 * 4096, s_b2, nullptr, nullptr, t);
    __syncthreads();

    // ---- single-head logits via mma: warps 0,1 (N=16 -> 2 ntiles) ----
    const int w = t >> 5, l = t & 31;
    if (w < 2) {
        const int r0 = l >> 2;
        const int cq = 2 * (l & 3);
        const int n  = w * 8 + r0;     // B-fragment column (ks row)
        float d0 = 0.f, d1 = 0.f, d2 = 0.f, d3 = 0.f;
#pragma unroll
        for (int kk = 0; kk < 8; kk++) {
            const int k = kk * 16;
            const unsigned a0 = pkx(&s_b1[r0][k + cq]);
            const unsigned a1 = pkx(&s_b1[r0 + 8][k + cq]);
            const unsigned a2 = pkx(&s_b1[r0][k + cq + 8]);
            const unsigned a3 = pkx(&s_b1[r0 + 8][k + cq + 8]);
            const unsigned bf0 = pkx(&s_b2[n][k + cq]);
            const unsigned bf1 = pkx(&s_b2[n][k + cq + 8]);
            mma16816(d0, d1, d2, d3, a0, a1, a2, a3, bf0, bf1);
        }
        const float invs = 0.08838834764831845f;  // 1/sqrt(128)
        const int c = w * 8 + cq;
        const unsigned m0 = s_mask[r0], m1 = s_mask[r0 + 8];
        const float o0 = ((m0 >> c) & 1u)       ? NEGV : 10.f * tanhf(d0 * invs);
        const float o1 = ((m0 >> (c + 1)) & 1u) ? NEGV : 10.f * tanhf(d1 * invs);
        const float o2 = ((m1 >> c) & 1u)       ? NEGV : 10.f * tanhf(d2 * invs);
        const float o3 = ((m1 >> (c + 1)) & 1u) ? NEGV : 10.f * tanhf(d3 * invs);
        float* ob = out + (size_t)b * (AA * AA);
        *reinterpret_cast<float2*>(&ob[r0 * AA + c])       = make_float2(o0, o1);
        *reinterpret_cast<float2*>(&ob[(r0 + 8) * AA + c]) = make_float2(o2, o3);
    }
}

extern "C" void kernel_launch(void* const* d_in, const int* in_sizes, int n_in,
                              void* d_out, int out_size) {
    const float* agent_embed = (const float*)d_in[0];
    const float* city_embed  = (const float*)d_in[1];
    const int*   acts        = (const int*)d_in[2];
    const float* Wq    = (const float*)d_in[3];
    const float* Wk    = (const float*)d_in[4];
    const float* Wv    = (const float*)d_in[5];
    const float* Wo    = (const float*)d_in[6];
    const float* ln1_g = (const float*)d_in[7];
    const float* ln1_b = (const float*)d_in[8];
    const float* W1    = (const float*)d_in[9];
    const float* b1v   = (const float*)d_in[10];
    const float* W2    = (const float*)d_in[11];
    const float* b2v   = (const float*)d_in[12];
    const float* ln2_g = (const float*)d_in[13];
    const float* ln2_b = (const float*)d_in[14];
    const float* Wqs   = (const float*)d_in[15];
    const float* Wks   = (const float*)d_in[16];

    const int B = in_sizes[0] / (AA * EE);

    pack_weights_kernel<<<256, 128>>>(Wq, Wk, Wv, Wo, W1, W2, Wqs, Wks);
    conflict_model_kernel<<<B, 128>>>(
        agent_embed, city_embed, acts,
        ln1_g, ln1_b, b1v, b2v, ln2_g, ln2_b,
        (float*)d_out);
}

// round 4
// speedup vs baseline: 8.3960x; 1.9929x over previous
#include <cuda_runtime.h>
#include <cuda_bf16.h>

#define AA 16      // agents
#define EE 128     // embed dim
#define EPH 136    // bf16 elems per smem row (272B: ldmatrix rows stagger 4 banks)
#define EPB 272    // row bytes
#define NB 2       // batches per CTA
#define NEGV (-1e9f)

// Packed bf16 weights: [m 8][nt 16][kk2 4][lane 32] uint4.
// .x={W[kb][n],W[kb+1][n]} .y={W[kb+8],W[kb+9]} .z={W[kb+16],W[kb+17]} .w={W[kb+24],W[kb+25]}
// where kb = kk2*32 + 2*(l&3), n = nt*8 + (l>>2).
__device__ uint4 g_wpack[8 * 16 * 4 * 32];

__device__ __forceinline__ unsigned pk2(float lo, float hi) {
    unsigned r;
    asm("cvt.rn.bf16x2.f32 %0, %1, %2;" : "=r"(r) : "f"(hi), "f"(lo));
    return r;
}
__device__ __forceinline__ float2 up2(unsigned u) {
    const __nv_bfloat162 h = *reinterpret_cast<const __nv_bfloat162*>(&u);
    return __bfloat1622float2(h);
}
__device__ __forceinline__ unsigned scvt(const void* p) {
    return (unsigned)__cvta_generic_to_shared(p);
}
__device__ __forceinline__ void ldsm4(unsigned& r0, unsigned& r1, unsigned& r2, unsigned& r3,
                                      unsigned a) {
    asm volatile("ldmatrix.sync.aligned.m8n8.x4.shared.b16 {%0,%1,%2,%3}, [%4];"
                 : "=r"(r0), "=r"(r1), "=r"(r2), "=r"(r3) : "r"(a));
}
__device__ __forceinline__ void ldsm4t(unsigned& r0, unsigned& r1, unsigned& r2, unsigned& r3,
                                       unsigned a) {
    asm volatile("ldmatrix.sync.aligned.m8n8.x4.trans.shared.b16 {%0,%1,%2,%3}, [%4];"
                 : "=r"(r0), "=r"(r1), "=r"(r2), "=r"(r3) : "r"(a));
}
__device__ __forceinline__ void ldsm2(unsigned& r0, unsigned& r1, unsigned a) {
    asm volatile("ldmatrix.sync.aligned.m8n8.x2.shared.b16 {%0,%1}, [%2];"
                 : "=r"(r0), "=r"(r1) : "r"(a));
}
__device__ __forceinline__ void mmaf(float d[4], unsigned a0, unsigned a1, unsigned a2,
                                     unsigned a3, unsigned b0, unsigned b1) {
    asm("mma.sync.aligned.m16n8k16.row.col.f32.bf16.bf16.f32 "
        "{%0,%1,%2,%3}, {%4,%5,%6,%7}, {%8,%9}, {%0,%1,%2,%3};"
        : "+f"(d[0]), "+f"(d[1]), "+f"(d[2]), "+f"(d[3])
        : "r"(a0), "r"(a1), "r"(a2), "r"(a3), "r"(b0), "r"(b1));
}

// ---- prepass: repack 8 fp32 [128][128] weights into uint4 fragment order ----
__global__ void __launch_bounds__(128) pack_weights_kernel(
    const float* __restrict__ Wq, const float* __restrict__ Wk,
    const float* __restrict__ Wv, const float* __restrict__ Wo,
    const float* __restrict__ W1, const float* __restrict__ W2,
    const float* __restrict__ Wqs, const float* __restrict__ Wks)
{
    const int idx = blockIdx.x * blockDim.x + threadIdx.x;   // 0..16383
    const int l  = idx & 31;
    const int k2 = (idx >> 5) & 3;
    const int nt = (idx >> 7) & 15;
    const int m  = idx >> 11;
    const float* W; float sc = 1.f;
    switch (m) {
        case 0: W = Wq; sc = 0.25f; break;   // fold 1/sqrt(dh)
        case 1: W = Wk; break;
        case 2: W = Wv; break;
        case 3: W = Wo; break;
        case 4: W = W1; break;
        case 5: W = W2; break;
        case 6: W = Wqs; break;
        default: W = Wks; break;
    }
    const int n  = nt * 8 + (l >> 2);
    const int kb = k2 * 32 + 2 * (l & 3);
    uint4 o;
    o.x = pk2(W[(kb +  0) * EE + n] * sc, W[(kb +  1) * EE + n] * sc);
    o.y = pk2(W[(kb +  8) * EE + n] * sc, W[(kb +  9) * EE + n] * sc);
    o.z = pk2(W[(kb + 16) * EE + n] * sc, W[(kb + 17) * EE + n] * sc);
    o.w = pk2(W[(kb + 24) * EE + n] * sc, W[(kb + 25) * EE + n] * sc);
    g_wpack[idx] = o;
}

enum { MRAW = 0, MRES = 1, MBRELU = 2, MBRES = 3 };

// Y[nb] = X[nb] @ W (+epilogue); all 4 warps, warp owns 32 cols, loops nb.
template<int MODE>
__device__ __forceinline__ void mm_phase(
    const __nv_bfloat16 (*Xs)[AA][EPH], __nv_bfloat16 (*Ys)[AA][EPH],
    const __nv_bfloat16 (*Rs)[AA][EPH], const float* __restrict__ bias,
    const uint4* __restrict__ Wp, int w, int l, unsigned offA, int r0, int cq)
{
    uint4 wf[4][4];
#pragma unroll
    for (int nt = 0; nt < 4; nt++)
#pragma unroll
        for (int k2 = 0; k2 < 4; k2++)
            wf[nt][k2] = __ldg(&Wp[(((w * 4 + nt) * 4) + k2) * 32 + l]);
    float2 bv[4];
    if (MODE == MBRELU || MODE == MBRES) {
#pragma unroll
        for (int nt = 0; nt < 4; nt++)
            bv[nt] = *reinterpret_cast<const float2*>(&bias[(w * 4 + nt) * 8 + cq]);
    }
#pragma unroll
    for (int nb = 0; nb < NB; nb++) {
        const unsigned xb = scvt(&Xs[nb][0][0]) + offA;
        float acc[4][4];
#pragma unroll
        for (int nt = 0; nt < 4; nt++) { acc[nt][0] = acc[nt][1] = acc[nt][2] = acc[nt][3] = 0.f; }
#pragma unroll
        for (int kk = 0; kk < 8; kk++) {
            unsigned a0, a1, a2, a3;
            ldsm4(a0, a1, a2, a3, xb + kk * 32);
#pragma unroll
            for (int nt = 0; nt < 4; nt++) {
                const uint4 q = wf[nt][kk >> 1];
                const unsigned b0 = (kk & 1) ? q.z : q.x;
                const unsigned b1 = (kk & 1) ? q.w : q.y;
                mmaf(acc[nt], a0, a1, a2, a3, b0, b1);
            }
        }
        char* yb = (char*)&Ys[nb][0][0];
        const char* rb = (MODE == MRES || MODE == MBRES) ? (const char*)&Rs[nb][0][0] : nullptr;
#pragma unroll
        for (int nt = 0; nt < 4; nt++) {
            const int colb = (w * 4 + nt) * 8 + cq;
            const unsigned off0 = r0 * EPB + colb * 2;
            const unsigned off1 = off0 + 8 * EPB;
            float x0 = acc[nt][0], x1 = acc[nt][1], x2 = acc[nt][2], x3 = acc[nt][3];
            if (MODE == MRES) {
                const float2 ra = up2(*(const unsigned*)(rb + off0));
                const float2 rc = up2(*(const unsigned*)(rb + off1));
                x0 += ra.x; x1 += ra.y; x2 += rc.x; x3 += rc.y;
            } else if (MODE == MBRELU) {
                x0 = fmaxf(x0 + bv[nt].x, 0.f); x1 = fmaxf(x1 + bv[nt].y, 0.f);
                x2 = fmaxf(x2 + bv[nt].x, 0.f); x3 = fmaxf(x3 + bv[nt].y, 0.f);
            } else if (MODE == MBRES) {
                const float2 ra = up2(*(const unsigned*)(rb + off0));
                const float2 rc = up2(*(const unsigned*)(rb + off1));
                x0 += bv[nt].x + ra.x; x1 += bv[nt].y + ra.y;
                x2 += bv[nt].x + rc.x; x3 += bv[nt].y + rc.y;
            }
            *(unsigned*)(yb + off0) = pk2(x0, x1);
            *(unsigned*)(yb + off1) = pk2(x2, x3);
        }
    }
}

// In-place LN; warp handles 8 rows of its batch (lane = fixed 4 cols).
__device__ __forceinline__ void ln_phase(__nv_bfloat16 (*X)[EPH], const float* __restrict__ g,
                                         const float* __restrict__ bsh, int half, int l)
{
    const float4 g4 = *reinterpret_cast<const float4*>(&g[l * 4]);
    const float4 b4 = *reinterpret_cast<const float4*>(&bsh[l * 4]);
#pragma unroll
    for (int rr = 0; rr < 8; rr++) {
        const int r = half * 8 + rr;
        char* rp = (char*)&X[r][0] + 8 * l;
        const uint2 p = *(const uint2*)rp;
        const float2 lo = up2(p.x), hi = up2(p.y);
        float s  = lo.x + lo.y + hi.x + hi.y;
        float ss = fmaf(lo.x, lo.x, fmaf(lo.y, lo.y, fmaf(hi.x, hi.x, hi.y * hi.y)));
#pragma unroll
        for (int o = 16; o > 0; o >>= 1) {
            s  += __shfl_xor_sync(0xffffffffu, s, o);
            ss += __shfl_xor_sync(0xffffffffu, ss, o);
        }
        const float mu  = s * (1.f / 128.f);
        const float var = ss * (1.f / 128.f) - mu * mu;
        const float inv = rsqrtf(var + 1e-5f);
        uint2 q;
        q.x = pk2((lo.x - mu) * inv * g4.x + b4.x, (lo.y - mu) * inv * g4.y + b4.y);
        q.y = pk2((hi.x - mu) * inv * g4.z + b4.z, (hi.y - mu) * inv * g4.w + b4.w);
        *(uint2*)rp = q;
    }
}

__global__ void __launch_bounds__(128)
conflict_model_kernel(
    const float* __restrict__ agent_embed,  // [B,16,128]
    const float* __restrict__ city_embed,   // [B,128,128]
    const int*   __restrict__ acts,         // [B,16]
    const float* __restrict__ ln1_g, const float* __restrict__ ln1_b,
    const float* __restrict__ b1v,  const float* __restrict__ b2v,
    const float* __restrict__ ln2_g, const float* __restrict__ ln2_b,
    float* __restrict__ out)                // [B,16,16]
{
    __shared__ __nv_bfloat16 sA[NB][AA][EPH];   // agent
    __shared__ __nv_bfloat16 sX[NB][AA][EPH];   // selected -> cac2
    __shared__ __nv_bfloat16 sB1[NB][AA][EPH];  // q -> attnO -> qs
    __shared__ __nv_bfloat16 sB2[NB][AA][EPH];  // k -> h -> ks
    __shared__ __nv_bfloat16 sB3[NB][AA][EPH];  // v -> ffn hidden
    __shared__ int      s_acts[NB][AA];
    __shared__ unsigned s_mask[NB][AA];

    const int t = threadIdx.x;
    const int w = t >> 5, l = t & 31;
    const int half = w & 1, nbw = w >> 1;
    const int r0 = l >> 2, cq = 2 * (l & 3);
    const int b0 = blockIdx.x * NB;

    // ldmatrix per-lane byte offsets
    const unsigned offA = (unsigned)(((l & 7) + ((l >> 3) & 1) * 8) * EPB + ((l >> 4) & 1) * 16);
    const unsigned offB = (unsigned)(((l & 7) + ((l >> 4) & 1) * 8) * EPB + ((l >> 3) & 1) * 16);

    // ---- acts + mask (warps 0,2) & agent rows (all warps) ----
    if (half == 0) {
        int av = (l < AA) ? acts[(b0 + nbw) * AA + l] : 0;
        unsigned m = 0;
#pragma unroll
        for (int j = 0; j < AA; j++) {
            const int aj = __shfl_sync(0xffffffffu, av, j);
            const bool conflict = (av == 0) ? (j == l) : (aj == av);
            if (!conflict) m |= (1u << j);
        }
        if (l < AA) { s_acts[nbw][l] = av; s_mask[nbw][l] = m; }
    }
#pragma unroll
    for (int rr = 0; rr < 8; rr++) {
        const int r = half * 8 + rr;
        const float4 v = *reinterpret_cast<const float4*>(
            agent_embed + ((size_t)(b0 + nbw) * AA + r) * EE + 4 * l);
        uint2 p; p.x = pk2(v.x, v.y); p.y = pk2(v.z, v.w);
        *(uint2*)((char*)&sA[nbw][r][0] + 8 * l) = p;
    }
    __syncthreads();
#pragma unroll
    for (int rr = 0; rr < 8; rr++) {
        const int r = half * 8 + rr;
        const int ci = s_acts[nbw][r];
        const float4 v = *reinterpret_cast<const float4*>(
            city_embed + ((size_t)(b0 + nbw) * 128 + ci) * EE + 4 * l);
        uint2 p; p.x = pk2(v.x, v.y); p.y = pk2(v.z, v.w);
        *(uint2*)((char*)&sX[nbw][r][0] + 8 * l) = p;
    }
    __syncthreads();

    // ---- q(scaled), k, v projections ----
    mm_phase<MRAW>(sX, sB1, nullptr, nullptr, g_wpack + 0 * 2048, w, l, offA, r0, cq);
    mm_phase<MRAW>(sA, sB2, nullptr, nullptr, g_wpack + 1 * 2048, w, l, offA, r0, cq);
    mm_phase<MRAW>(sA, sB3, nullptr, nullptr, g_wpack + 2 * 2048, w, l, offA, r0, cq);
    __syncthreads();

    // ---- MMA attention: warp = (batch nbw, heads half*4..+4) ----
    {
        const unsigned qb = scvt(&sB1[nbw][0][0]);
        const unsigned kb = scvt(&sB2[nbw][0][0]);
        const unsigned vb = scvt(&sB3[nbw][0][0]);
        const unsigned m0 = s_mask[nbw][r0], m1 = s_mask[nbw][r0 + 8];
#pragma unroll
        for (int hh = 0; hh < 4; hh++) {
            const int h = half * 4 + hh;
            const unsigned cb = 32u * h;  // 16h elems * 2B
            unsigned a0, a1, a2, a3, k0, k1, k2, k3;
            ldsm4(a0, a1, a2, a3, qb + offA + cb);
            ldsm4(k0, k1, k2, k3, kb + offB + cb);
            float s0[4] = {0, 0, 0, 0}, s1[4] = {0, 0, 0, 0};
            mmaf(s0, a0, a1, a2, a3, k0, k1);
            mmaf(s1, a0, a1, a2, a3, k2, k3);
            // mask: s0 keys cq,cq+1 ; s1 keys 8+cq,9+cq ; rows r0 / r0+8
            if ((m0 >> cq) & 1)       s0[0] = NEGV;
            if ((m0 >> (cq + 1)) & 1) s0[1] = NEGV;
            if ((m1 >> cq) & 1)       s0[2] = NEGV;
            if ((m1 >> (cq + 1)) & 1) s0[3] = NEGV;
            if ((m0 >> (cq + 8)) & 1) s1[0] = NEGV;
            if ((m0 >> (cq + 9)) & 1) s1[1] = NEGV;
            if ((m1 >> (cq + 8)) & 1) s1[2] = NEGV;
            if ((m1 >> (cq + 9)) & 1) s1[3] = NEGV;
            float mx0 = fmaxf(fmaxf(s0[0], s0[1]), fmaxf(s1[0], s1[1]));
            float mx1 = fmaxf(fmaxf(s0[2], s0[3]), fmaxf(s1[2], s1[3]));
            mx0 = fmaxf(mx0, __shfl_xor_sync(0xffffffffu, mx0, 1));
            mx0 = fmaxf(mx0, __shfl_xor_sync(0xffffffffu, mx0, 2));
            mx1 = fmaxf(mx1, __shfl_xor_sync(0xffffffffu, mx1, 1));
            mx1 = fmaxf(mx1, __shfl_xor_sync(0xffffffffu, mx1, 2));
            s0[0] = __expf(s0[0] - mx0); s0[1] = __expf(s0[1] - mx0);
            s1[0] = __expf(s1[0] - mx0); s1[1] = __expf(s1[1] - mx0);
            s0[2] = __expf(s0[2] - mx1); s0[3] = __expf(s0[3] - mx1);
            s1[2] = __expf(s1[2] - mx1); s1[3] = __expf(s1[3] - mx1);
            float sm0 = s0[0] + s0[1] + s1[0] + s1[1];
            float sm1 = s0[2] + s0[3] + s1[2] + s1[3];
            sm0 += __shfl_xor_sync(0xffffffffu, sm0, 1);
            sm0 += __shfl_xor_sync(0xffffffffu, sm0, 2);
            sm1 += __shfl_xor_sync(0xffffffffu, sm1, 1);
            sm1 += __shfl_xor_sync(0xffffffffu, sm1, 2);
            const float inv0 = 1.f / sm0, inv1 = 1.f / sm1;
            // P fragments (unnormalized; fold inv into O)
            const unsigned p0 = pk2(s0[0], s0[1]);
            const unsigned p1 = pk2(s0[2], s0[3]);
            const unsigned p2 = pk2(s1[0], s1[1]);
            const unsigned p3 = pk2(s1[2], s1[3]);
            unsigned v0, v1, v2, v3;
            ldsm4t(v0, v1, v2, v3, vb + offA + cb);
            float o0[4] = {0, 0, 0, 0}, o1[4] = {0, 0, 0, 0};
            mmaf(o0, p0, p1, p2, p3, v0, v1);
            mmaf(o1, p0, p1, p2, p3, v2, v3);
            char* yb = (char*)&sB1[nbw][0][0];
            const unsigned c0 = r0 * EPB + (16 * h + cq) * 2;
            const unsigned c1 = c0 + 8 * EPB;
            *(unsigned*)(yb + c0)      = pk2(o0[0] * inv0, o0[1] * inv0);
            *(unsigned*)(yb + c1)      = pk2(o0[2] * inv1, o0[3] * inv1);
            *(unsigned*)(yb + c0 + 16) = pk2(o1[0] * inv0, o1[1] * inv0);
            *(unsigned*)(yb + c1 + 16) = pk2(o1[2] * inv1, o1[3] * inv1);
        }
    }
    __syncthreads();

    // ---- attnO @ Wo + selected -> sB2; LN1 ----
    mm_phase<MRES>(sB1, sB2, sX, nullptr, g_wpack + 3 * 2048, w, l, offA, r0, cq);
    __syncthreads();
    ln_phase(sB2[nbw], ln1_g, ln1_b, half, l);
    __syncthreads();

    // ---- FFN hidden -> sB3 ----
    mm_phase<MBRELU>(sB2, sB3, nullptr, b1v, g_wpack + 4 * 2048, w, l, offA, r0, cq);
    __syncthreads();

    // ---- FFN out + b2 + h -> sX; LN2 ----
    mm_phase<MBRES>(sB3, sX, sB2, b2v, g_wpack + 5 * 2048, w, l, offA, r0, cq);
    __syncthreads();
    ln_phase(sX[nbw], ln2_g, ln2_b, half, l);
    __syncthreads();

    // ---- qs -> sB1, ks -> sB2 ----
    mm_phase<MRAW>(sX, sB1, nullptr, nullptr, g_wpack + 6 * 2048, w, l, offA, r0, cq);
    mm_phase<MRAW>(sA, sB2, nullptr, nullptr, g_wpack + 7 * 2048, w, l, offA, r0, cq);
    __syncthreads();

    // ---- logits: warp = (batch nbw, n-tile half) ----
    {
        const unsigned qb = scvt(&sB1[nbw][0][0]);
        const unsigned kb = scvt(&sB2[nbw][0][0]) + half * 8 * EPB;
        const unsigned offB2 = (unsigned)((l & 7) * EPB + ((l >> 3) & 1) * 16);
        float d[4] = {0, 0, 0, 0};
#pragma unroll
        for (int kk = 0; kk < 8; kk++) {
            unsigned a0, a1, a2, a3, bb0, bb1;
            ldsm4(a0, a1, a2, a3, qb + offA + kk * 32);
            ldsm2(bb0, bb1, kb + offB2 + kk * 32);
            mmaf(d, a0, a1, a2, a3, bb0, bb1);
        }
        const float invs = 0.08838834764831845f;  // 1/sqrt(128)
        const int colb = half * 8 + cq;
        const unsigned m0 = s_mask[nbw][r0], m1 = s_mask[nbw][r0 + 8];
        const float o0 = ((m0 >> colb) & 1u)       ? NEGV : 10.f * tanhf(d[0] * invs);
        const float o1 = ((m0 >> (colb + 1)) & 1u) ? NEGV : 10.f * tanhf(d[1] * invs);
        const float o2 = ((m1 >> colb) & 1u)       ? NEGV : 10.f * tanhf(d[2] * invs);
        const float o3 = ((m1 >> (colb + 1)) & 1u) ? NEGV : 10.f * tanhf(d[3] * invs);
        float* ob = out + (size_t)(b0 + nbw) * (AA * AA);
        *reinterpret_cast<float2*>(&ob[r0 * AA + colb])       = make_float2(o0, o1);
        *reinterpret_cast<float2*>(&ob[(r0 + 8) * AA + colb]) = make_float2(o2, o3);
    }
}

extern "C" void kernel_launch(void* const* d_in, const int* in_sizes, int n_in,
                              void* d_out, int out_size) {
    const float* agent_embed = (const float*)d_in[0];
    const float* city_embed  = (const float*)d_in[1];
    const int*   acts        = (const int*)d_in[2];
    const float* Wq    = (const float*)d_in[3];
    const float* Wk    = (const float*)d_in[4];
    const float* Wv    = (const float*)d_in[5];
    const float* Wo    = (const float*)d_in[6];
    const float* ln1_g = (const float*)d_in[7];
    const float* ln1_b = (const float*)d_in[8];
    const float* W1    = (const float*)d_in[9];
    const float* b1v   = (const float*)d_in[10];
    const float* W2    = (const float*)d_in[11];
    const float* b2v   = (const float*)d_in[12];
    const float* ln2_g = (const float*)d_in[13];
    const float* ln2_b = (const float*)d_in[14];
    const float* Wqs   = (const float*)d_in[15];
    const float* Wks   = (const float*)d_in[16];

    const int B = in_sizes[0] / (AA * EE);

    pack_weights_kernel<<<128, 128>>>(Wq, Wk, Wv, Wo, W1, W2, Wqs, Wks);
    conflict_model_kernel<<<B / NB, 128>>>(
        agent_embed, city_embed, acts,
        ln1_g, ln1_b, b1v, b2v, ln2_g, ln2_b,
        (float*)d_out);
}

// round 5
// speedup vs baseline: 9.0000x; 1.0719x over previous
#include <cuda_runtime.h>
#include <cuda_bf16.h>

#define AA 16      // agents
#define EE 128     // embed dim
#define EPH 136    // bf16 elems per smem row (272B: ldmatrix rows stagger banks)
#define EPB 272    // row bytes
#define NB 2       // batches per CTA
#define NEGV (-1e9f)

// Packed bf16 weights: [m 8][nt 16][kk2 4][lane 32] uint4.
// .x={W[kb][n],W[kb+1][n]} .y={W[kb+8],W[kb+9]} .z={W[kb+16],W[kb+17]} .w={W[kb+24],W[kb+25]}
// where kb = kk2*32 + 2*(l&3), n = nt*8 + (l>>2).
__device__ uint4 g_wpack[8 * 16 * 4 * 32];

__device__ __forceinline__ unsigned pk2(float lo, float hi) {
    unsigned r;
    asm("cvt.rn.bf16x2.f32 %0, %1, %2;" : "=r"(r) : "f"(hi), "f"(lo));
    return r;
}
__device__ __forceinline__ float2 up2(unsigned u) {
    const __nv_bfloat162 h = *reinterpret_cast<const __nv_bfloat162*>(&u);
    return __bfloat1622float2(h);
}
__device__ __forceinline__ float tanh_fast(float x) {
    float r;
    asm("tanh.approx.f32 %0, %1;" : "=f"(r) : "f"(x));
    return r;
}
__device__ __forceinline__ unsigned scvt(const void* p) {
    return (unsigned)__cvta_generic_to_shared(p);
}
__device__ __forceinline__ void ldsm4(unsigned& r0, unsigned& r1, unsigned& r2, unsigned& r3,
                                      unsigned a) {
    asm volatile("ldmatrix.sync.aligned.m8n8.x4.shared.b16 {%0,%1,%2,%3}, [%4];"
                 : "=r"(r0), "=r"(r1), "=r"(r2), "=r"(r3) : "r"(a));
}
__device__ __forceinline__ void ldsm4t(unsigned& r0, unsigned& r1, unsigned& r2, unsigned& r3,
                                       unsigned a) {
    asm volatile("ldmatrix.sync.aligned.m8n8.x4.trans.shared.b16 {%0,%1,%2,%3}, [%4];"
                 : "=r"(r0), "=r"(r1), "=r"(r2), "=r"(r3) : "r"(a));
}
__device__ __forceinline__ void ldsm2(unsigned& r0, unsigned& r1, unsigned a) {
    asm volatile("ldmatrix.sync.aligned.m8n8.x2.shared.b16 {%0,%1}, [%2];"
                 : "=r"(r0), "=r"(r1) : "r"(a));
}
__device__ __forceinline__ void mmaf(float d[4], unsigned a0, unsigned a1, unsigned a2,
                                     unsigned a3, unsigned b0, unsigned b1) {
    asm("mma.sync.aligned.m16n8k16.row.col.f32.bf16.bf16.f32 "
        "{%0,%1,%2,%3}, {%4,%5,%6,%7}, {%8,%9}, {%0,%1,%2,%3};"
        : "+f"(d[0]), "+f"(d[1]), "+f"(d[2]), "+f"(d[3])
        : "r"(a0), "r"(a1), "r"(a2), "r"(a3), "r"(b0), "r"(b1));
}

// ---- prepass: repack 8 fp32 [128][128] weights into uint4 fragment order ----
__global__ void __launch_bounds__(128) pack_weights_kernel(
    const float* __restrict__ Wq, const float* __restrict__ Wk,
    const float* __restrict__ Wv, const float* __restrict__ Wo,
    const float* __restrict__ W1, const float* __restrict__ W2,
    const float* __restrict__ Wqs, const float* __restrict__ Wks)
{
    const int idx = blockIdx.x * blockDim.x + threadIdx.x;   // 0..16383
    const int l  = idx & 31;
    const int k2 = (idx >> 5) & 3;
    const int nt = (idx >> 7) & 15;
    const int m  = idx >> 11;
    const float* W; float sc = 1.f;
    switch (m) {
        case 0: W = Wq; sc = 0.25f; break;   // fold 1/sqrt(dh)
        case 1: W = Wk; break;
        case 2: W = Wv; break;
        case 3: W = Wo; break;
        case 4: W = W1; break;
        case 5: W = W2; break;
        case 6: W = Wqs; break;
        default: W = Wks; break;
    }
    const int n  = nt * 8 + (l >> 2);
    const int kb = k2 * 32 + 2 * (l & 3);
    uint4 o;
    o.x = pk2(W[(kb +  0) * EE + n] * sc, W[(kb +  1) * EE + n] * sc);
    o.y = pk2(W[(kb +  8) * EE + n] * sc, W[(kb +  9) * EE + n] * sc);
    o.z = pk2(W[(kb + 16) * EE + n] * sc, W[(kb + 17) * EE + n] * sc);
    o.w = pk2(W[(kb + 24) * EE + n] * sc, W[(kb + 25) * EE + n] * sc);
    g_wpack[idx] = o;
}

enum { MRAW = 0, MRES = 1, MBRELU = 2, MBRES = 3 };

// Y[nb] = X[nb] @ W (+epilogue); warp owns 32 cols; k2-outer so only 4 weight
// uint4s are live at a time (register pressure), reused across both batches.
template<int MODE>
__device__ __forceinline__ void mm_phase(
    const __nv_bfloat16 (*Xs)[AA][EPH], __nv_bfloat16 (*Ys)[AA][EPH],
    const __nv_bfloat16 (*Rs)[AA][EPH], const float* __restrict__ bias,
    const uint4* __restrict__ Wp, int w, int l, unsigned offA, int r0, int cq)
{
    float acc[NB][4][4];
#pragma unroll
    for (int nb = 0; nb < NB; nb++)
#pragma unroll
        for (int nt = 0; nt < 4; nt++) {
            acc[nb][nt][0] = acc[nb][nt][1] = acc[nb][nt][2] = acc[nb][nt][3] = 0.f;
        }
    const unsigned xb0 = scvt(&Xs[0][0][0]) + offA;
    const unsigned xb1 = scvt(&Xs[1][0][0]) + offA;
#pragma unroll
    for (int k2 = 0; k2 < 4; k2++) {
        uint4 wfr[4];
#pragma unroll
        for (int nt = 0; nt < 4; nt++)
            wfr[nt] = __ldg(&Wp[(((w * 4 + nt) * 4) + k2) * 32 + l]);
#pragma unroll
        for (int nb = 0; nb < NB; nb++) {
            const unsigned xb = nb ? xb1 : xb0;
            unsigned a0, a1, a2, a3, c0, c1, c2, c3;
            ldsm4(a0, a1, a2, a3, xb + (2 * k2) * 32);
            ldsm4(c0, c1, c2, c3, xb + (2 * k2 + 1) * 32);
#pragma unroll
            for (int nt = 0; nt < 4; nt++) {
                mmaf(acc[nb][nt], a0, a1, a2, a3, wfr[nt].x, wfr[nt].y);
                mmaf(acc[nb][nt], c0, c1, c2, c3, wfr[nt].z, wfr[nt].w);
            }
        }
    }
#pragma unroll
    for (int nb = 0; nb < NB; nb++) {
        char* yb = (char*)&Ys[nb][0][0];
        const char* rb = (MODE == MRES || MODE == MBRES) ? (const char*)&Rs[nb][0][0] : nullptr;
#pragma unroll
        for (int nt = 0; nt < 4; nt++) {
            const int colb = (w * 4 + nt) * 8 + cq;
            const unsigned off0 = r0 * EPB + colb * 2;
            const unsigned off1 = off0 + 8 * EPB;
            float x0 = acc[nb][nt][0], x1 = acc[nb][nt][1];
            float x2 = acc[nb][nt][2], x3 = acc[nb][nt][3];
            if (MODE == MRES) {
                const float2 ra = up2(*(const unsigned*)(rb + off0));
                const float2 rc = up2(*(const unsigned*)(rb + off1));
                x0 += ra.x; x1 += ra.y; x2 += rc.x; x3 += rc.y;
            } else if (MODE == MBRELU) {
                const float2 bv = *reinterpret_cast<const float2*>(&bias[colb]);
                x0 = fmaxf(x0 + bv.x, 0.f); x1 = fmaxf(x1 + bv.y, 0.f);
                x2 = fmaxf(x2 + bv.x, 0.f); x3 = fmaxf(x3 + bv.y, 0.f);
            } else if (MODE == MBRES) {
                const float2 bv = *reinterpret_cast<const float2*>(&bias[colb]);
                const float2 ra = up2(*(const unsigned*)(rb + off0));
                const float2 rc = up2(*(const unsigned*)(rb + off1));
                x0 += bv.x + ra.x; x1 += bv.y + ra.y;
                x2 += bv.x + rc.x; x3 += bv.y + rc.y;
            }
            *(unsigned*)(yb + off0) = pk2(x0, x1);
            *(unsigned*)(yb + off1) = pk2(x2, x3);
        }
    }
}

// In-place LN; warp handles 8 rows of its batch (lane = fixed 4 cols).
__device__ __forceinline__ void ln_phase(__nv_bfloat16 (*X)[EPH], const float* __restrict__ g,
                                         const float* __restrict__ bsh, int half, int l)
{
    const float4 g4 = *reinterpret_cast<const float4*>(&g[l * 4]);
    const float4 b4 = *reinterpret_cast<const float4*>(&bsh[l * 4]);
#pragma unroll
    for (int rr = 0; rr < 8; rr++) {
        const int r = half * 8 + rr;
        char* rp = (char*)&X[r][0] + 8 * l;
        const uint2 p = *(const uint2*)rp;
        const float2 lo = up2(p.x), hi = up2(p.y);
        float s  = lo.x + lo.y + hi.x + hi.y;
        float ss = fmaf(lo.x, lo.x, fmaf(lo.y, lo.y, fmaf(hi.x, hi.x, hi.y * hi.y)));
#pragma unroll
        for (int o = 16; o > 0; o >>= 1) {
            s  += __shfl_xor_sync(0xffffffffu, s, o);
            ss += __shfl_xor_sync(0xffffffffu, ss, o);
        }
        const float mu  = s * (1.f / 128.f);
        const float var = ss * (1.f / 128.f) - mu * mu;
        const float inv = rsqrtf(var + 1e-5f);
        uint2 q;
        q.x = pk2((lo.x - mu) * inv * g4.x + b4.x, (lo.y - mu) * inv * g4.y + b4.y);
        q.y = pk2((hi.x - mu) * inv * g4.z + b4.z, (hi.y - mu) * inv * g4.w + b4.w);
        *(uint2*)rp = q;
    }
}

__global__ void __launch_bounds__(128, 5)
conflict_model_kernel(
    const float* __restrict__ agent_embed,  // [B,16,128]
    const float* __restrict__ city_embed,   // [B,128,128]
    const int*   __restrict__ acts,         // [B,16]
    const float* __restrict__ ln1_g, const float* __restrict__ ln1_b,
    const float* __restrict__ b1v,  const float* __restrict__ b2v,
    const float* __restrict__ ln2_g, const float* __restrict__ ln2_b,
    float* __restrict__ out)                // [B,16,16]
{
    __shared__ __nv_bfloat16 sA[NB][AA][EPH];   // agent
    __shared__ __nv_bfloat16 sX[NB][AA][EPH];   // selected -> cac2
    __shared__ __nv_bfloat16 sB1[NB][AA][EPH];  // q -> attnO -> qs
    __shared__ __nv_bfloat16 sB2[NB][AA][EPH];  // k -> h -> ks
    __shared__ __nv_bfloat16 sB3[NB][AA][EPH];  // v -> ffn hidden
    __shared__ int      s_acts[NB][AA];
    __shared__ unsigned s_mask[NB][AA];

    const int t = threadIdx.x;
    const int w = t >> 5, l = t & 31;
    const int half = w & 1, nbw = w >> 1;
    const int r0 = l >> 2, cq = 2 * (l & 3);
    const int b0 = blockIdx.x * NB;

    // ldmatrix per-lane byte offsets
    const unsigned offA = (unsigned)(((l & 7) + ((l >> 3) & 1) * 8) * EPB + ((l >> 4) & 1) * 16);
    const unsigned offB = (unsigned)(((l & 7) + ((l >> 4) & 1) * 8) * EPB + ((l >> 3) & 1) * 16);

    // ---- acts + mask (warps 0,2) & agent rows (all warps) ----
    if (half == 0) {
        int av = (l < AA) ? acts[(b0 + nbw) * AA + l] : 0;
        unsigned m = 0;
#pragma unroll
        for (int j = 0; j < AA; j++) {
            const int aj = __shfl_sync(0xffffffffu, av, j);
            const bool conflict = (av == 0) ? (j == l) : (aj == av);
            if (!conflict) m |= (1u << j);
        }
        if (l < AA) { s_acts[nbw][l] = av; s_mask[nbw][l] = m; }
    }
#pragma unroll
    for (int rr = 0; rr < 8; rr++) {
        const int r = half * 8 + rr;
        const float4 v = *reinterpret_cast<const float4*>(
            agent_embed + ((size_t)(b0 + nbw) * AA + r) * EE + 4 * l);
        uint2 p; p.x = pk2(v.x, v.y); p.y = pk2(v.z, v.w);
        *(uint2*)((char*)&sA[nbw][r][0] + 8 * l) = p;
    }
    __syncthreads();
#pragma unroll
    for (int rr = 0; rr < 8; rr++) {
        const int r = half * 8 + rr;
        const int ci = s_acts[nbw][r];
        const float4 v = *reinterpret_cast<const float4*>(
            city_embed + ((size_t)(b0 + nbw) * 128 + ci) * EE + 4 * l);
        uint2 p; p.x = pk2(v.x, v.y); p.y = pk2(v.z, v.w);
        *(uint2*)((char*)&sX[nbw][r][0] + 8 * l) = p;
    }
    __syncthreads();

    // ---- q(scaled), k, v projections ----
    mm_phase<MRAW>(sX, sB1, nullptr, nullptr, g_wpack + 0 * 2048, w, l, offA, r0, cq);
    mm_phase<MRAW>(sA, sB2, nullptr, nullptr, g_wpack + 1 * 2048, w, l, offA, r0, cq);
    mm_phase<MRAW>(sA, sB3, nullptr, nullptr, g_wpack + 2 * 2048, w, l, offA, r0, cq);
    __syncthreads();

    // ---- MMA attention: warp = (batch nbw, heads half*4..+4) ----
    {
        const unsigned qb = scvt(&sB1[nbw][0][0]);
        const unsigned kb = scvt(&sB2[nbw][0][0]);
        const unsigned vb = scvt(&sB3[nbw][0][0]);
        const unsigned m0 = s_mask[nbw][r0], m1 = s_mask[nbw][r0 + 8];
#pragma unroll
        for (int hh = 0; hh < 4; hh++) {
            const int h = half * 4 + hh;
            const unsigned cb = 32u * h;  // 16h elems * 2B
            unsigned a0, a1, a2, a3, k0, k1, k2, k3;
            ldsm4(a0, a1, a2, a3, qb + offA + cb);
            ldsm4(k0, k1, k2, k3, kb + offB + cb);
            float s0[4] = {0, 0, 0, 0}, s1[4] = {0, 0, 0, 0};
            mmaf(s0, a0, a1, a2, a3, k0, k1);
            mmaf(s1, a0, a1, a2, a3, k2, k3);
            if ((m0 >> cq) & 1)       s0[0] = NEGV;
            if ((m0 >> (cq + 1)) & 1) s0[1] = NEGV;
            if ((m1 >> cq) & 1)       s0[2] = NEGV;
            if ((m1 >> (cq + 1)) & 1) s0[3] = NEGV;
            if ((m0 >> (cq + 8)) & 1) s1[0] = NEGV;
            if ((m0 >> (cq + 9)) & 1) s1[1] = NEGV;
            if ((m1 >> (cq + 8)) & 1) s1[2] = NEGV;
            if ((m1 >> (cq + 9)) & 1) s1[3] = NEGV;
            float mx0 = fmaxf(fmaxf(s0[0], s0[1]), fmaxf(s1[0], s1[1]));
            float mx1 = fmaxf(fmaxf(s0[2], s0[3]), fmaxf(s1[2], s1[3]));
            mx0 = fmaxf(mx0, __shfl_xor_sync(0xffffffffu, mx0, 1));
            mx0 = fmaxf(mx0, __shfl_xor_sync(0xffffffffu, mx0, 2));
            mx1 = fmaxf(mx1, __shfl_xor_sync(0xffffffffu, mx1, 1));
            mx1 = fmaxf(mx1, __shfl_xor_sync(0xffffffffu, mx1, 2));
            s0[0] = __expf(s0[0] - mx0); s0[1] = __expf(s0[1] - mx0);
            s1[0] = __expf(s1[0] - mx0); s1[1] = __expf(s1[1] - mx0);
            s0[2] = __expf(s0[2] - mx1); s0[3] = __expf(s0[3] - mx1);
            s1[2] = __expf(s1[2] - mx1); s1[3] = __expf(s1[3] - mx1);
            float sm0 = s0[0] + s0[1] + s1[0] + s1[1];
            float sm1 = s0[2] + s0[3] + s1[2] + s1[3];
            sm0 += __shfl_xor_sync(0xffffffffu, sm0, 1);
            sm0 += __shfl_xor_sync(0xffffffffu, sm0, 2);
            sm1 += __shfl_xor_sync(0xffffffffu, sm1, 1);
            sm1 += __shfl_xor_sync(0xffffffffu, sm1, 2);
            const float inv0 = 1.f / sm0, inv1 = 1.f / sm1;
            const unsigned p0 = pk2(s0[0], s0[1]);
            const unsigned p1 = pk2(s0[2], s0[3]);
            const unsigned p2 = pk2(s1[0], s1[1]);
            const unsigned p3 = pk2(s1[2], s1[3]);
            unsigned v0, v1, v2, v3;
            ldsm4t(v0, v1, v2, v3, vb + offA + cb);
            float o0[4] = {0, 0, 0, 0}, o1[4] = {0, 0, 0, 0};
            mmaf(o0, p0, p1, p2, p3, v0, v1);
            mmaf(o1, p0, p1, p2, p3, v2, v3);
            char* yb = (char*)&sB1[nbw][0][0];
            const unsigned c0 = r0 * EPB + (16 * h + cq) * 2;
            const unsigned c1 = c0 + 8 * EPB;
            *(unsigned*)(yb + c0)      = pk2(o0[0] * inv0, o0[1] * inv0);
            *(unsigned*)(yb + c1)      = pk2(o0[2] * inv1, o0[3] * inv1);
            *(unsigned*)(yb + c0 + 16) = pk2(o1[0] * inv0, o1[1] * inv0);
            *(unsigned*)(yb + c1 + 16) = pk2(o1[2] * inv1, o1[3] * inv1);
        }
    }
    __syncthreads();

    // ---- attnO @ Wo + selected -> sB2; LN1 ----
    mm_phase<MRES>(sB1, sB2, sX, nullptr, g_wpack + 3 * 2048, w, l, offA, r0, cq);
    __syncthreads();
    ln_phase(sB2[nbw], ln1_g, ln1_b, half, l);
    __syncthreads();

    // ---- FFN hidden -> sB3 ----
    mm_phase<MBRELU>(sB2, sB3, nullptr, b1v, g_wpack + 4 * 2048, w, l, offA, r0, cq);
    __syncthreads();

    // ---- FFN out + b2 + h -> sX; LN2 ----
    mm_phase<MBRES>(sB3, sX, sB2, b2v, g_wpack + 5 * 2048, w, l, offA, r0, cq);
    __syncthreads();
    ln_phase(sX[nbw], ln2_g, ln2_b, half, l);
    __syncthreads();

    // ---- qs -> sB1, ks -> sB2 ----
    mm_phase<MRAW>(sX, sB1, nullptr, nullptr, g_wpack + 6 * 2048, w, l, offA, r0, cq);
    mm_phase<MRAW>(sA, sB2, nullptr, nullptr, g_wpack + 7 * 2048, w, l, offA, r0, cq);
    __syncthreads();

    // ---- logits: warp = (batch nbw, n-tile half) ----
    {
        const unsigned qb = scvt(&sB1[nbw][0][0]);
        const unsigned kb = scvt(&sB2[nbw][0][0]) + half * 8 * EPB;
        const unsigned offB2 = (unsigned)((l & 7) * EPB + ((l >> 3) & 1) * 16);
        float d[4] = {0, 0, 0, 0};
#pragma unroll
        for (int kk = 0; kk < 8; kk++) {
            unsigned a0, a1, a2, a3, bb0, bb1;
            ldsm4(a0, a1, a2, a3, qb + offA + kk * 32);
            ldsm2(bb0, bb1, kb + offB2 + kk * 32);
            mmaf(d, a0, a1, a2, a3, bb0, bb1);
        }
        const float invs = 0.08838834764831845f;  // 1/sqrt(128)
        const int colb = half * 8 + cq;
        const unsigned m0 = s_mask[nbw][r0], m1 = s_mask[nbw][r0 + 8];
        const float o0 = ((m0 >> colb) & 1u)       ? NEGV : 10.f * tanh_fast(d[0] * invs);
        const float o1 = ((m0 >> (colb + 1)) & 1u) ? NEGV : 10.f * tanh_fast(d[1] * invs);
        const float o2 = ((m1 >> colb) & 1u)       ? NEGV : 10.f * tanh_fast(d[2] * invs);
        const float o3 = ((m1 >> (colb + 1)) & 1u) ? NEGV : 10.f * tanh_fast(d[3] * invs);
        float* ob = out + (size_t)(b0 + nbw) * (AA * AA);
        *reinterpret_cast<float2*>(&ob[r0 * AA + colb])       = make_float2(o0, o1);
        *reinterpret_cast<float2*>(&ob[(r0 + 8) * AA + colb]) = make_float2(o2, o3);
    }
}

extern "C" void kernel_launch(void* const* d_in, const int* in_sizes, int n_in,
                              void* d_out, int out_size) {
    const float* agent_embed = (const float*)d_in[0];
    const float* city_embed  = (const float*)d_in[1];
    const int*   acts        = (const int*)d_in[2];
    const float* Wq    = (const float*)d_in[3];
    const float* Wk    = (const float*)d_in[4];
    const float* Wv    = (const float*)d_in[5];
    const float* Wo    = (const float*)d_in[6];
    const float* ln1_g = (const float*)d_in[7];
    const float* ln1_b = (const float*)d_in[8];
    const float* W1    = (const float*)d_in[9];
    const float* b1v   = (const float*)d_in[10];
    const float* W2    = (const float*)d_in[11];
    const float* b2v   = (const float*)d_in[12];
    const float* ln2_g = (const float*)d_in[13];
    const float* ln2_b = (const float*)d_in[14];
    const float* Wqs   = (const float*)d_in[15];
    const float* Wks   = (const float*)d_in[16];

    const int B = in_sizes[0] / (AA * EE);

    pack_weights_kernel<<<128, 128>>>(Wq, Wk, Wv, Wo, W1, W2, Wqs, Wks);
    conflict_model_kernel<<<B / NB, 128>>>(
        agent_embed, city_embed, acts,
        ln1_g, ln1_b, b1v, b2v, ln2_g, ln2_b,
        (float*)d_out);
}